// round 17
// baseline (speedup 1.0000x reference)
#include <cuda_runtime.h>
#include <cuda_fp16.h>
#include <stdint.h>
#include <math.h>

// ---------------- problem constants ----------------
#define CDIM    256
#define HDIM    56
#define WDIM    56
#define HW      3136
#define L_TOTAL 25088
#define DDIM    2304

// ---------------- scratch: single fp16 planes ----------------
__device__ __align__(128) __half g_t [(size_t)L_TOTAL * DDIM];
__device__ __align__(128) __half g_h [(size_t)L_TOTAL * CDIM];
__device__ __align__(128) __half g_p [(size_t)L_TOTAL * DDIM];
__device__ __align__(128) __half g_w1[(size_t)CDIM * DDIM];
__device__ __align__(128) __half g_w2[(size_t)DDIM * CDIM];
__device__ __align__(128) __half g_w3[(size_t)CDIM * DDIM];

// ---------------- helpers ----------------
__device__ __forceinline__ uint32_t smem_u32(const void* p) {
    uint32_t a;
    asm("{ .reg .u64 t; cvta.to.shared.u64 t, %1; cvt.u32.u64 %0, t; }" : "=r"(a) : "l"(p));
    return a;
}
__device__ __forceinline__ void ldm_x4(uint32_t* r, uint32_t addr) {
    asm volatile("ldmatrix.sync.aligned.m8n8.x4.shared.b16 {%0,%1,%2,%3}, [%4];"
        : "=r"(r[0]), "=r"(r[1]), "=r"(r[2]), "=r"(r[3]) : "r"(addr));
}
__device__ __forceinline__ void mma16816(float* d, const uint32_t* a, uint32_t b0, uint32_t b1) {
    asm volatile("mma.sync.aligned.m16n8k16.row.col.f32.f16.f16.f32 "
        "{%0,%1,%2,%3}, {%4,%5,%6,%7}, {%8,%9}, {%0,%1,%2,%3};"
        : "+f"(d[0]), "+f"(d[1]), "+f"(d[2]), "+f"(d[3])
        : "r"(a[0]), "r"(a[1]), "r"(a[2]), "r"(a[3]), "r"(b0), "r"(b1));
}
__device__ __forceinline__ void cp_async16(uint32_t dst, const void* src) {
    asm volatile("cp.async.cg.shared.global [%0], [%1], 16;" :: "r"(dst), "l"(src));
}
#define CP_COMMIT() asm volatile("cp.async.commit_group;" ::: "memory")
#define CP_WAIT2()  asm volatile("cp.async.wait_group 2;" ::: "memory")
#define CP_WAIT0()  asm volatile("cp.async.wait_group 0;" ::: "memory")

// ---------------- K0: tiled unfold -> fp16 plane ----------------
__global__ __launch_bounds__(256) void unfold_tiled(const float* __restrict__ x,
    __half* __restrict__ t)
{
    __shared__ __half xs[64 * 3 * 58];
    const int chunk = blockIdx.x;
    const int h     = blockIdx.y;
    const int b     = blockIdx.z;
    const int c0    = chunk * 64;
    const int tid   = threadIdx.x;

    for (int i = tid; i < 64 * 3; i += 256) {
        xs[i * 58 + 0]  = __float2half(0.f);
        xs[i * 58 + 57] = __float2half(0.f);
    }
    for (int i = tid; i < 64 * 3 * 56; i += 256) {
        int w = i % 56;
        int rest = i / 56;
        int hh = rest % 3;
        int c  = rest / 3;
        int gh = h + hh - 1;
        float v = 0.f;
        if (gh >= 0 && gh < HDIM)
            v = x[((size_t)(b * CDIM + c0 + c) * HDIM + gh) * WDIM + w];
        xs[(c * 3 + hh) * 58 + (w + 1)] = __float2half(v);
    }
    __syncthreads();

    const int lbase = b * HW + h * WDIM;
    for (int pid = tid; pid < 56 * 288; pid += 256) {
        int j = pid % 288;
        int w = pid / 288;
        int e0 = 2 * j;
        __half v0, v1;
        {
            int e = e0;
            int c = e / 9, r = e - 9 * c;
            int di = r / 3, dj = r - 3 * di;
            v0 = xs[(c * 3 + di) * 58 + (w + dj)];
        }
        {
            int e = e0 + 1;
            int c = e / 9, r = e - 9 * c;
            int di = r / 3, dj = r - 3 * di;
            v1 = xs[(c * 3 + di) * 58 + (w + dj)];
        }
        __half2 o; o.x = v0; o.y = v1;
        *(__half2*)(t + (size_t)(lbase + w) * DDIM + chunk * 576 + e0) = o;
    }
}

// ---------------- fused weight transpose ----------------
__global__ __launch_bounds__(256) void wtrans_all(
    const float* __restrict__ W1, const float* __restrict__ W2, const float* __restrict__ W3,
    __half* __restrict__ o1, __half* __restrict__ o2, __half* __restrict__ o3)
{
    const int seg = blockIdx.x / 1152;
    const int blk = blockIdx.x % 1152;
    const float* W = (seg == 0) ? W1 : (seg == 1) ? W2 : W3;
    __half* o      = (seg == 0) ? o1 : (seg == 1) ? o2 : o3;
    const int K    = (seg == 1) ? CDIM : DDIM;
    const int N    = (seg == 1) ? DDIM : CDIM;

    int t = blk * 256 + threadIdx.x;
    int NP = N * (K / 2);
    if (t >= NP) return;
    int kp = t % (K / 2), n = t / (K / 2);
    int k0 = kp * 2;
    __half2 h2;
    h2.x = __float2half(W[(size_t)k0 * N + n]);
    h2.y = __float2half(W[(size_t)(k0 + 1) * N + n]);
    *(__half2*)(o + (size_t)n * K + k0) = h2;
}

// ---------------- 4-stage single-sync fp16 mma.sync GEMM ----------------
// C = epi(A @ B^T + bias); A [M,K] fp16, B [N,K] fp16.
// BM=128 BN=128 BK=32, 256 threads, warps 4m x 2n.
// One __syncthreads per iter; loads for stage it+3 issued before compute of stage it.
// MODE 1: relu -> fp16
// MODE 2: sigmoid * X -> fp16; X tile (32KB) prefetched into smem during mainloop
// MODE 3: fp32 + bias
#define STAGE_B 16384
#define NSTAGE  4
#define XBUF_OFF (NSTAGE * STAGE_B)        // 65536
#define SMEM_BYTES   (NSTAGE * STAGE_B)    // 65536
#define SMEM2_BYTES  (XBUF_OFF + 32768)    // 98304

template<int MODE>
__global__ __launch_bounds__(256, 2) void gemm_mma(
    const __half* __restrict__ A, const __half* __restrict__ B,
    const float* __restrict__ bias,
    const __half* __restrict__ X,
    __half* __restrict__ Oh, float* __restrict__ Of,
    int M, int N, int Kd)
{
    extern __shared__ __align__(128) char smem[];
    const uint32_t sb = smem_u32(smem);

    const int tid  = threadIdx.x;
    const int lane = tid & 31;
    const int wid  = tid >> 5;
    const int warp_m = wid & 3;
    const int warp_n = wid >> 2;
    const int m0 = blockIdx.y * 128;
    const int n0 = blockIdx.x * 128;

    const int lr = tid >> 2;
    const int lc = tid & 3;

    float acc[2][8][4];
    #pragma unroll
    for (int a = 0; a < 2; a++)
        #pragma unroll
        for (int b = 0; b < 8; b++)
            #pragma unroll
            for (int c = 0; c < 4; c++) acc[a][b][c] = 0.f;

    const int grp = lane >> 3, r8 = lane & 7;
    const int rowoff = ((grp & 1) << 3) + r8;
    const int cg = grp >> 1;
    int offA[2], swA[2], offB[4], swB[4];
    #pragma unroll
    for (int tm = 0; tm < 2; tm++) {
        int r = warp_m * 32 + tm * 16 + rowoff;
        offA[tm] = r * 64; swA[tm] = (r >> 1) & 3;
    }
    #pragma unroll
    for (int p = 0; p < 4; p++) {
        int r = warp_n * 64 + p * 16 + rowoff;
        offB[p] = r * 64; swB[p] = (r >> 1) & 3;
    }

    const int NIT = Kd >> 5;

    auto load_stage = [&](int st, int k0) {
        uint32_t stb = sb + st * STAGE_B;
        #pragma unroll
        for (int i = 0; i < 4; i++) {
            int plane = i >> 1;
            int r = ((i & 1) << 6) + lr;
            uint32_t dst = stb + plane * 8192 + r * 64 + ((lc ^ ((r >> 1) & 3)) << 4);
            const char* src = (plane == 0)
                ? (const char*)(A + (size_t)(m0 + r) * Kd + k0 + lc * 8)
                : (const char*)(B + (size_t)(n0 + r) * Kd + k0 + lc * 8);
            cp_async16(dst, src);
        }
    };

    // prologue: stages 0..2 (3 groups in flight)
    #pragma unroll
    for (int s = 0; s < NSTAGE - 1; s++) {
        load_stage(s, s * 32);
        CP_COMMIT();
    }

    for (int it = 0; it < NIT; it++) {
        CP_WAIT2();            // stage it arrived (<=2 younger groups pending)
        __syncthreads();       // all warps done computing stage it-1

        // issue loads for stage it+3 into slot (it+3)%4 == (it-1)%4 (freed by sync)
        int ls = it + NSTAGE - 1;
        if (ls < NIT) load_stage(ls & 3, ls * 32);
        if (MODE == 2 && it < 8) {
            // ride 4KB of the X tile per iter: 2048 chunks = 128 rows x 16 chunks
            int idx = it * 256 + tid;
            int row = idx >> 4;
            int c16 = idx & 15;
            cp_async16(sb + XBUF_OFF + row * 256 + c16 * 16,
                       (const char*)(X + (size_t)(m0 + row) * N + n0 + c16 * 8));
        }
        CP_COMMIT();

        const uint32_t stb = sb + (it & 3) * STAGE_B;
        #pragma unroll
        for (int ks = 0; ks < 2; ks++) {
            uint32_t ah[2][4], bh[4][4];
            #pragma unroll
            for (int tm = 0; tm < 2; tm++) {
                uint32_t colA = (uint32_t)((((ks << 1) | cg) ^ swA[tm]) << 4);
                ldm_x4(ah[tm], stb + offA[tm] + colA);
            }
            #pragma unroll
            for (int p = 0; p < 4; p++) {
                uint32_t colB = (uint32_t)((((ks << 1) | cg) ^ swB[p]) << 4);
                ldm_x4(bh[p], stb + 8192 + offB[p] + colB);
            }
            #pragma unroll
            for (int tm = 0; tm < 2; tm++)
                #pragma unroll
                for (int tn = 0; tn < 8; tn++) {
                    int p = tn >> 1, o = tn & 1;
                    mma16816(acc[tm][tn], ah[tm], bh[p][o], bh[p][2 + o]);
                }
        }
    }

    if (MODE == 2) {
        CP_WAIT0();
    }
    __syncthreads();

    // ---------------- epilogue ----------------
    const int qr = lane >> 2;
    const int qc = (lane & 3) * 2;
    #pragma unroll
    for (int tm = 0; tm < 2; tm++) {
        int mb = m0 + warp_m * 32 + tm * 16;
        #pragma unroll
        for (int tn = 0; tn < 8; tn++) {
            int n = n0 + warp_n * 64 + tn * 8 + qc;
            float bx = bias[n], by = bias[n + 1];
            #pragma unroll
            for (int half = 0; half < 2; half++) {
                int m = mb + qr + half * 8;
                float vx = acc[tm][tn][half * 2 + 0] + bx;
                float vy = acc[tm][tn][half * 2 + 1] + by;
                size_t o = (size_t)m * N + n;
                if (MODE == 1) {
                    __half2 w;
                    w.x = __float2half(fmaxf(vx, 0.f));
                    w.y = __float2half(fmaxf(vy, 0.f));
                    *(__half2*)(Oh + o) = w;
                } else if (MODE == 2) {
                    float sx = 1.f / (1.f + __expf(-vx));
                    float sy = 1.f / (1.f + __expf(-vy));
                    __half2 tv = *(__half2*)(smem + XBUF_OFF + (m - m0) * 256 + (n - n0) * 2);
                    __half2 w;
                    w.x = __float2half(__half2float(tv.x) * sx);
                    w.y = __float2half(__half2float(tv.y) * sy);
                    *(__half2*)(Oh + o) = w;
                } else {
                    float2 w; w.x = vx; w.y = vy;
                    *(float2*)(Of + o) = w;
                }
            }
        }
    }
}

// ---------------- host launch ----------------
extern "C" void kernel_launch(void* const* d_in, const int* in_sizes, int n_in,
                              void* d_out, int out_size)
{
    const float* x  = (const float*)d_in[0];
    const float* W1 = (const float*)d_in[1];
    const float* b1 = (const float*)d_in[2];
    const float* W2 = (const float*)d_in[3];
    const float* b2 = (const float*)d_in[4];
    const float* W3 = (const float*)d_in[5];
    const float* b3 = (const float*)d_in[6];
    float* out = (float*)d_out;

    __half *pt, *ph, *pp, *w1, *w2, *w3;
    cudaGetSymbolAddress((void**)&pt, g_t);
    cudaGetSymbolAddress((void**)&ph, g_h);
    cudaGetSymbolAddress((void**)&pp, g_p);
    cudaGetSymbolAddress((void**)&w1, g_w1);
    cudaGetSymbolAddress((void**)&w2, g_w2);
    cudaGetSymbolAddress((void**)&w3, g_w3);

    cudaFuncSetAttribute(gemm_mma<1>, cudaFuncAttributeMaxDynamicSharedMemorySize, SMEM_BYTES);
    cudaFuncSetAttribute(gemm_mma<2>, cudaFuncAttributeMaxDynamicSharedMemorySize, SMEM2_BYTES);
    cudaFuncSetAttribute(gemm_mma<3>, cudaFuncAttributeMaxDynamicSharedMemorySize, SMEM_BYTES);

    unfold_tiled<<<dim3(4, 56, 8), 256>>>(x, pt);
    wtrans_all<<<3 * 1152, 256>>>(W1, W2, W3, w1, w2, w3);

    // K1: h = relu(t @ W1 + b1)        [25088 x 256],  K=2304
    gemm_mma<1><<<dim3(CDIM / 128, L_TOTAL / 128), 256, SMEM_BYTES>>>(
        pt, w1, b1, nullptr, ph, nullptr, L_TOTAL, CDIM, DDIM);
    // K2: p = t * sigmoid(h @ W2 + b2) [25088 x 2304], K=256 — X prefetched to smem
    gemm_mma<2><<<dim3(DDIM / 128, L_TOTAL / 128), 256, SMEM2_BYTES>>>(
        ph, w2, b2, pt, pp, nullptr, L_TOTAL, DDIM, CDIM);
    // K3: out = p @ W3 + b3            [25088 x 256],  K=2304
    gemm_mma<3><<<dim3(CDIM / 128, L_TOTAL / 128), 256, SMEM_BYTES>>>(
        pp, w3, b3, nullptr, nullptr, out, L_TOTAL, CDIM, DDIM);
}